// round 8
// baseline (speedup 1.0000x reference)
#include <cuda_runtime.h>
#include <cstdint>

#define T 256
#define RPB 256
#define NCOLS 14
#define IN_BYTES  (RPB * NCOLS * 4)   // 14336 B per full tile
#define OUT_BYTES (RPB * 3 * 4)       //  3072 B per full tile
#define GRID 912                      // 152 SMs * 6 CTAs (smem-limited)

__device__ __forceinline__ uint32_t smem_u32(const void* p) {
    uint32_t a;
    asm("{ .reg .u64 t; cvta.to.shared.u64 t, %1; cvt.u32.u64 %0, t; }" : "=r"(a) : "l"(p));
    return a;
}

#define MBAR_WAIT(mb, ph) do {                                             \
    uint32_t _done = 0;                                                    \
    while (!_done) {                                                       \
        asm volatile("{\n\t.reg .pred p;\n\t"                              \
            "mbarrier.try_wait.parity.acquire.cta.shared::cta.b64 p, [%1], %2, 0x989680;\n\t" \
            "selp.b32 %0, 1, 0, p;\n\t}"                                   \
            : "=r"(_done) : "r"(mb), "r"(ph) : "memory");                  \
    }                                                                      \
} while (0)

__global__ __launch_bounds__(T, 6)
void indicator_kernel(const float* __restrict__ in, float* __restrict__ out,
                      int NT, int n) {
    __shared__ alignas(128) float s_in[2][RPB * NCOLS];   // 2 x 14336 B
    __shared__ alignas(128) float s_out[2][RPB * 3];      // 2 x  3072 B
    __shared__ alignas(8)  uint64_t mbar[2];

    const int tid = threadIdx.x;
    const uint32_t mb[2] = { smem_u32(&mbar[0]), smem_u32(&mbar[1]) };
    const uint32_t sin[2] = { smem_u32(s_in[0]), smem_u32(s_in[1]) };

    if (tid == 0) {
        asm volatile("mbarrier.init.shared.b64 [%0], 1;" :: "r"(mb[0]) : "memory");
        asm volatile("mbarrier.init.shared.b64 [%0], 1;" :: "r"(mb[1]) : "memory");
    }
    __syncthreads();

    // ---- prologue: issue loads for my first (up to) 2 tiles ----
    if (tid == 0) {
        #pragma unroll
        for (int k = 0; k < 2; k++) {
            int t = blockIdx.x + k * GRID;
            if (t < NT) {
                uint32_t bytes = (t == NT - 1) ? (uint32_t)(n - t * RPB) * NCOLS * 4
                                               : (uint32_t)IN_BYTES;
                asm volatile("mbarrier.arrive.expect_tx.shared.b64 _, [%0], %1;"
                             :: "r"(mb[k]), "r"(bytes) : "memory");
                const char* src = (const char*)in + (size_t)t * IN_BYTES;
                asm volatile(
                    "cp.async.bulk.shared::cta.global.mbarrier::complete_tx::bytes [%0], [%1], %2, [%3];"
                    :: "r"(sin[k]), "l"(src), "r"(bytes), "r"(mb[k]) : "memory");
            }
        }
    }

    int it = 0;
    for (int t = blockIdx.x; t < NT; t += GRID, it++) {
        const int s  = it & 1;
        const int ph = (it >> 1) & 1;

        MBAR_WAIT(mb[s], ph);

        // ---- compute (one row per thread) into registers ----
        const int row = t * RPB + tid;
        float o0 = 0.f, o1 = 0.f, o2 = 0.f;
        if (row < n) {
            const float*  r  = &s_in[s][tid * NCOLS];
            const float2* r2 = (const float2*)r;
            const float2 oc  = r2[0];   // cols 0,1
            const float  lw  = r[5];
            const float  uw  = r[6];
            const float2 ms  = r2[4];   // cols 8,9
            const float2 sbv = r2[5];   // cols 10,11
            const float2 mbl = r2[6];   // cols 12,13
            const float ha_open = oc.x, ha_close = oc.y;
            const float ma = ms.x, srsi = ms.y;
            const float ssig = sbv.x, bu = sbv.y;
            const float bm = mbl.x,  bl = mbl.y;

            const bool  bullish = ha_close > ha_open;
            const bool  bearish = ha_close < ha_open;
            const float body    = fabsf(ha_close - ha_open);
            const bool  sb = bullish && (body > 0.5f) && (uw < 1e-6f);
            const bool  sB = bearish && (body > 0.5f) && (lw < 1e-6f);

            const float ha2 = sb ? 0.8f : 0.0f;
            const float ha0 = sB ? 0.8f : 0.0f;

            const float width = (bu - bl) / bm;
            const float pp    = (ha_close - bl) / (bu - bl);
            const bool  sqexp = (width < 0.1f) && (width > 0.2f);  // structurally false, fidelity
            const float sqf   = sqexp ? 0.9f : 0.0f;

            const bool pp_lo = pp < 0.2f;
            const bool pp_hi = pp > 0.8f;
            const float bb2 = (pp_lo ? 0.8f : 0.0f) + sqf;
            const float bb0 = (pp_hi ? 0.8f : 0.0f) + sqf;

            const float st2 = (srsi < 0.2f) ? 0.8f : 0.0f;
            const float st0 = (srsi > 0.8f) ? 0.8f : 0.0f;

            const bool  ma_up = ma > 0.1f;
            const bool  ma_dn = ma < -0.1f;
            const float ma2 = ma_up ? 0.7f : 0.0f;
            const float ma0 = ma_dn ? 0.7f : 0.0f;

            const bool st_dn = ssig < -0.1f;
            const bool st_up = ssig > 0.1f;

            const bool long_sig  = ((int)sb + (int)ma_up + (int)st_dn + (int)pp_lo) >= 3;
            const bool short_sig = ((int)sB + (int)ma_dn + (int)st_up + (int)pp_hi) >= 3;

            const float hms2 = long_sig  ? 0.9f : 0.0f;
            const float hms0 = short_sig ? 0.9f : 0.0f;

            const float col0 = ha0 + ma0 + st0 + bb0 + 2.0f * hms0;
            const float col2 = ha2 + ma2 + st2 + bb2 + 2.0f * hms2;
            const float col1 = 1.5f;

            const float m  = fmaxf(fmaxf(col0, col2), col1);
            const float e0 = __expf(col0 - m);
            const float e1 = __expf(col1 - m);
            const float e2 = __expf(col2 - m);
            const float inv = 1.0f / (e0 + e1 + e2);
            o0 = e0 * inv; o1 = e1 * inv; o2 = e2 * inv;
        }

        // ensure the bulk store that used s_out[s] (2 iters ago) has drained
        if (tid == 0) asm volatile("cp.async.bulk.wait_group 1;" ::: "memory");
        __syncthreads();

        if (row < n) {
            s_out[s][tid * 3 + 0] = o0;
            s_out[s][tid * 3 + 1] = o1;
            s_out[s][tid * 3 + 2] = o2;
        }
        __syncthreads();   // s_out[s] written, s_in[s] reads complete

        if (tid == 0) {
            asm volatile("fence.proxy.async.shared::cta;" ::: "memory");
            const uint32_t obytes = (t == NT - 1) ? (uint32_t)(n - t * RPB) * 3 * 4
                                                  : (uint32_t)OUT_BYTES;
            char* dst = (char*)out + (size_t)t * OUT_BYTES;
            const uint32_t sout = smem_u32(s_out[s]);
            asm volatile("cp.async.bulk.global.shared::cta.bulk_group [%0], [%1], %2;"
                         :: "l"(dst), "r"(sout), "r"(obytes) : "memory");
            asm volatile("cp.async.bulk.commit_group;" ::: "memory");

            // prefetch tile t + 2*GRID into the stage we just vacated
            const int tn = t + 2 * GRID;
            if (tn < NT) {
                uint32_t bytes = (tn == NT - 1) ? (uint32_t)(n - tn * RPB) * NCOLS * 4
                                                : (uint32_t)IN_BYTES;
                asm volatile("mbarrier.arrive.expect_tx.shared.b64 _, [%0], %1;"
                             :: "r"(mb[s]), "r"(bytes) : "memory");
                const char* src = (const char*)in + (size_t)tn * IN_BYTES;
                asm volatile(
                    "cp.async.bulk.shared::cta.global.mbarrier::complete_tx::bytes [%0], [%1], %2, [%3];"
                    :: "r"(sin[s]), "l"(src), "r"(bytes), "r"(mb[s]) : "memory");
            }
        }
    }

    // drain outstanding stores before exit
    if (tid == 0) asm volatile("cp.async.bulk.wait_group 0;" ::: "memory");
}

extern "C" void kernel_launch(void* const* d_in, const int* in_sizes, int n_in,
                              void* d_out, int out_size) {
    const float* in = (const float*)d_in[0];
    float* out = (float*)d_out;
    const int n  = in_sizes[0] / NCOLS;        // 2,000,000 rows
    const int NT = (n + RPB - 1) / RPB;        // 7813 tiles
    indicator_kernel<<<GRID, T>>>(in, out, NT, n);
}